// round 1
// baseline (speedup 1.0000x reference)
#include <cuda_runtime.h>

// ---------------- scratch (device globals; no allocation allowed) ----------------
#define Bb 4
#define Ss 2048
#define Dd 1024
__device__ float g_qkv[(long long)Bb * Ss * (3 * Dd)];   // [B,S,3D] 100.7 MB
__device__ float g_scores[(long long)Bb * Ss * Ss];      // [B,S,S]  67 MB
__device__ float g_attn[(long long)Bb * Ss * Dd];        // 33.5 MB
__device__ float g_x2[(long long)Bb * Ss * Dd];          // 33.5 MB
__device__ float g_h[(long long)Bb * Ss * Dd];           // 33.5 MB

// ---------------- SGEMM: 128x128x8, 256 threads, 8x8 microtile ----------------
#define BM 128
#define BN 128
#define BK 8
#define TM 8
#define TN 8

enum { EPI_NONE = 0, EPI_SCORES = 1, EPI_BIAS_RES = 2, EPI_BIAS_RELU = 3 };

template <int EPI, bool TB>
__global__ __launch_bounds__(256, 2) void sgemm_kernel(
    const float* __restrict__ A, int lda, long long sA,
    const float* __restrict__ B, int ldb, long long sB,
    float* __restrict__ C, int ldc, long long sC,
    int M, int N, int K,
    const float* __restrict__ bias,
    const float* __restrict__ res, long long sRes)
{
    __shared__ float As[2][BK][BM];
    __shared__ float Bs[2][BK][BN];

    const int z = blockIdx.z;
    A += (long long)z * sA;
    B += (long long)z * sB;
    C += (long long)z * sC;
    if (EPI == EPI_BIAS_RES) res += (long long)z * sRes;

    const int tid = threadIdx.x;
    const int tx = tid & 15;        // 0..15 -> 8 cols each
    const int ty = tid >> 4;        // 0..15 -> 8 rows each
    const int blockRow = blockIdx.y * BM;
    const int blockCol = blockIdx.x * BN;

    // A tile loader: 128 rows x 8 k, float4 along k
    const int aRow = tid >> 1;
    const int aK = (tid & 1) * 4;
    const float* Aptr = A + (long long)(blockRow + aRow) * lda + aK;

    // B tile loader
    int bRow, bCol;
    const float* Bptr;
    if (!TB) { // B is [K x N] row-major: float4 along n
        bRow = tid >> 5;            // k in [0,8)
        bCol = (tid & 31) * 4;      // n
        Bptr = B + (long long)bRow * ldb + blockCol + bCol;
    } else {   // B is [N x K] row-major (we need B[k][n] = Bt[n][k]): float4 along k
        bRow = (tid & 1) * 4;       // k chunk
        bCol = tid >> 1;            // n in [0,128)
        Bptr = B + (long long)(blockCol + bCol) * ldb + bRow;
    }

    float acc[TM][TN];
#pragma unroll
    for (int i = 0; i < TM; i++)
#pragma unroll
        for (int j = 0; j < TN; j++) acc[i][j] = 0.f;

    // ---- load tile 0 ----
    float4 aReg = *(const float4*)Aptr;
    float4 bReg = *(const float4*)Bptr;
    As[0][aK + 0][aRow] = aReg.x;
    As[0][aK + 1][aRow] = aReg.y;
    As[0][aK + 2][aRow] = aReg.z;
    As[0][aK + 3][aRow] = aReg.w;
    if (!TB) {
        *(float4*)&Bs[0][bRow][bCol] = bReg;
    } else {
        Bs[0][bRow + 0][bCol] = bReg.x;
        Bs[0][bRow + 1][bCol] = bReg.y;
        Bs[0][bRow + 2][bCol] = bReg.z;
        Bs[0][bRow + 3][bCol] = bReg.w;
    }
    __syncthreads();

    const int nTiles = K / BK;
    int buf = 0;
    for (int t = 0; t < nTiles; t++) {
        // prefetch next tile into registers
        if (t + 1 < nTiles) {
            aReg = *(const float4*)(Aptr + (t + 1) * BK);
            if (!TB) bReg = *(const float4*)(Bptr + (long long)(t + 1) * BK * ldb);
            else     bReg = *(const float4*)(Bptr + (t + 1) * BK);
        }
        // compute current tile
#pragma unroll
        for (int kk = 0; kk < BK; kk++) {
            float af[TM], bf[TN];
            *(float4*)&af[0] = *(float4*)&As[buf][kk][ty * TM];
            *(float4*)&af[4] = *(float4*)&As[buf][kk][ty * TM + 4];
            *(float4*)&bf[0] = *(float4*)&Bs[buf][kk][tx * TN];
            *(float4*)&bf[4] = *(float4*)&Bs[buf][kk][tx * TN + 4];
#pragma unroll
            for (int i = 0; i < TM; i++)
#pragma unroll
                for (int j = 0; j < TN; j++) acc[i][j] += af[i] * bf[j];
        }
        // stage next tile into the other buffer
        if (t + 1 < nTiles) {
            const int nb = buf ^ 1;
            As[nb][aK + 0][aRow] = aReg.x;
            As[nb][aK + 1][aRow] = aReg.y;
            As[nb][aK + 2][aRow] = aReg.z;
            As[nb][aK + 3][aRow] = aReg.w;
            if (!TB) {
                *(float4*)&Bs[nb][bRow][bCol] = bReg;
            } else {
                Bs[nb][bRow + 0][bCol] = bReg.x;
                Bs[nb][bRow + 1][bCol] = bReg.y;
                Bs[nb][bRow + 2][bCol] = bReg.z;
                Bs[nb][bRow + 3][bCol] = bReg.w;
            }
            __syncthreads();
            buf = nb;
        }
    }

    // ---- epilogue ----
#pragma unroll
    for (int i = 0; i < TM; i++) {
        const int gm = blockRow + ty * TM + i;
        float vals[TN];
#pragma unroll
        for (int j = 0; j < TN; j++) {
            const int gn = blockCol + tx * TN + j;
            float v = acc[i][j];
            if (EPI == EPI_SCORES) {
                v *= 0.5f;                               // 1/sqrt(B=4)
                v = (gn >= gm && v != 0.0f) ? v : -9e15f; // triu + (==0 -> mask)
            } else if (EPI == EPI_BIAS_RES) {
                v += bias[gn] + res[(long long)gm * ldc + gn];
            } else if (EPI == EPI_BIAS_RELU) {
                v = fmaxf(v + bias[gn], 0.0f);
            }
            vals[j] = v;
        }
        float* cp = C + (long long)gm * ldc + blockCol + tx * TN;
        *(float4*)&cp[0] = *(float4*)&vals[0];
        *(float4*)&cp[4] = *(float4*)&vals[4];
    }
}

// ---------------- row softmax over 2048 elements ----------------
__inline__ __device__ float warpMaxf(float v) {
#pragma unroll
    for (int o = 16; o > 0; o >>= 1) v = fmaxf(v, __shfl_xor_sync(0xffffffffu, v, o));
    return v;
}
__inline__ __device__ float warpSumf(float v) {
#pragma unroll
    for (int o = 16; o > 0; o >>= 1) v += __shfl_xor_sync(0xffffffffu, v, o);
    return v;
}

__global__ __launch_bounds__(256) void softmax2048(float* __restrict__ S)
{
    __shared__ float red[8];
    __shared__ float bcast;
    const long long row = blockIdx.x;
    float* p = S + row * 2048;
    const int tid = threadIdx.x;
    const int lane = tid & 31, wid = tid >> 5;

    float v[8];
    *(float4*)&v[0] = *(const float4*)(p + tid * 8);
    *(float4*)&v[4] = *(const float4*)(p + tid * 8 + 4);

    float m = v[0];
#pragma unroll
    for (int i = 1; i < 8; i++) m = fmaxf(m, v[i]);
    m = warpMaxf(m);
    if (lane == 0) red[wid] = m;
    __syncthreads();
    if (tid == 0) {
        float t = red[0];
#pragma unroll
        for (int i = 1; i < 8; i++) t = fmaxf(t, red[i]);
        bcast = t;
    }
    __syncthreads();
    m = bcast;

    float s = 0.f;
#pragma unroll
    for (int i = 0; i < 8; i++) { v[i] = expf(v[i] - m); s += v[i]; }
    s = warpSumf(s);
    __syncthreads();
    if (lane == 0) red[wid] = s;
    __syncthreads();
    if (tid == 0) {
        float t = 0.f;
#pragma unroll
        for (int i = 0; i < 8; i++) t += red[i];
        bcast = t;
    }
    __syncthreads();
    const float inv = 1.0f / bcast;
#pragma unroll
    for (int i = 0; i < 8; i++) v[i] *= inv;
    *(float4*)(p + tid * 8) = *(float4*)&v[0];
    *(float4*)(p + tid * 8 + 4) = *(float4*)&v[4];
}

// ---------------- launch ----------------
extern "C" void kernel_launch(void* const* d_in, const int* in_sizes, int n_in,
                              void* d_out, int out_size)
{
    const float* x     = (const float*)d_in[0];
    const float* wqkv  = (const float*)d_in[1];
    const float* w_lin = (const float*)d_in[2];
    const float* b_lin = (const float*)d_in[3];
    const float* w_ff1 = (const float*)d_in[4];
    const float* b_ff1 = (const float*)d_in[5];
    const float* w_ff2 = (const float*)d_in[6];
    const float* b_ff2 = (const float*)d_in[7];
    float* out = (float*)d_out;

    static float *qkv = nullptr, *scores = nullptr, *attn = nullptr, *x2 = nullptr, *hb = nullptr;
    if (!qkv) {
        cudaGetSymbolAddress((void**)&qkv, g_qkv);
        cudaGetSymbolAddress((void**)&scores, g_scores);
        cudaGetSymbolAddress((void**)&attn, g_attn);
        cudaGetSymbolAddress((void**)&x2, g_x2);
        cudaGetSymbolAddress((void**)&hb, g_h);
    }

    const long long sQKV = (long long)Ss * 3 * Dd;   // per-batch stride in qkv
    const long long sSC  = (long long)Ss * Ss;
    const long long sAO  = (long long)Ss * Dd;
    dim3 blk(256);

    // G1: qkv = x @ wqkv   [8192x3072]
    sgemm_kernel<EPI_NONE, false><<<dim3(3072 / BN, (Bb * Ss) / BM, 1), blk>>>(
        x, Dd, 0, wqkv, 3 * Dd, 0, qkv, 3 * Dd, 0,
        Bb * Ss, 3 * Dd, Dd, nullptr, nullptr, 0);

    // G2: scores = 0.5 * Q @ K^T  + triu/zero mask   (per batch)
    sgemm_kernel<EPI_SCORES, true><<<dim3(Ss / BN, Ss / BM, Bb), blk>>>(
        qkv, 3 * Dd, sQKV,            // Q
        qkv + Dd, 3 * Dd, sQKV,       // K (row-major [S,D] -> NT)
        scores, Ss, sSC,
        Ss, Ss, Dd, nullptr, nullptr, 0);

    // softmax rows
    softmax2048<<<Bb * Ss, 256>>>(scores);

    // G3: attn = att @ V   (per batch)
    sgemm_kernel<EPI_NONE, false><<<dim3(Dd / BN, Ss / BM, Bb), blk>>>(
        scores, Ss, sSC,
        qkv + 2 * Dd, 3 * Dd, sQKV,
        attn, Dd, sAO,
        Ss, Dd, Ss, nullptr, nullptr, 0);

    // G4: x2 = attn @ w_lin + b_lin + x
    sgemm_kernel<EPI_BIAS_RES, false><<<dim3(Dd / BN, (Bb * Ss) / BM, 1), blk>>>(
        attn, Dd, 0, w_lin, Dd, 0, x2, Dd, 0,
        Bb * Ss, Dd, Dd, b_lin, x, 0);

    // G5: h = relu(x2 @ w_ff1 + b_ff1)
    sgemm_kernel<EPI_BIAS_RELU, false><<<dim3(Dd / BN, (Bb * Ss) / BM, 1), blk>>>(
        x2, Dd, 0, w_ff1, Dd, 0, hb, Dd, 0,
        Bb * Ss, Dd, Dd, b_ff1, nullptr, 0);

    // G6: out = h @ w_ff2 + b_ff2 + x2
    sgemm_kernel<EPI_BIAS_RES, false><<<dim3(Dd / BN, (Bb * Ss) / BM, 1), blk>>>(
        hb, Dd, 0, w_ff2, Dd, 0, out, Dd, 0,
        Bb * Ss, Dd, Dd, b_ff2, x2, 0);
}

// round 5
// speedup vs baseline: 6.2398x; 6.2398x over previous
#include <cuda_runtime.h>
#include <cuda_fp16.h>
#include <cstdint>

// ---------------- scratch (device globals; no allocation allowed) ----------------
#define Bb 4
#define Ss 2048
#define Dd 1024
__device__ unsigned short g_xh[(long long)Bb * Ss * Dd];
__device__ unsigned short g_wqkvh[(long long)Dd * 3 * Dd];
__device__ unsigned short g_wlh[(long long)Dd * Dd];
__device__ unsigned short g_wf1h[(long long)Dd * Dd];
__device__ unsigned short g_wf2h[(long long)Dd * Dd];
__device__ unsigned short g_qkvh[(long long)Bb * Ss * 3 * Dd];
__device__ float          g_scores[(long long)Bb * Ss * Ss];
__device__ unsigned short g_atth[(long long)Bb * Ss * Ss];
__device__ unsigned short g_attnh[(long long)Bb * Ss * Dd];
__device__ float          g_x2[(long long)Bb * Ss * Dd];
__device__ unsigned short g_x2h[(long long)Bb * Ss * Dd];
__device__ unsigned short g_hh[(long long)Bb * Ss * Dd];

// ---------------- fp16 tensor-core GEMM: 128x128x32, 256 threads ----------------
#define BM 128
#define BN 128
#define BK 32
#define AST 40     // A smem row stride (fp16): 80B -> conflict-free ldmatrix phases
#define BSTT 40    // B smem stride, TB ([N][K]) layout
#define BSTN 136   // B smem stride, non-TB ([K][N]) layout: 272B -> conflict-free

enum { EPI_H16 = 0, EPI_SCORES = 1, EPI_DUAL = 2, EPI_RELU_H16 = 3, EPI_RES_F32 = 4 };

__device__ __forceinline__ void cp16(uint32_t dst, const void* src) {
    asm volatile("cp.async.cg.shared.global [%0], [%1], 16;\n" :: "r"(dst), "l"(src) : "memory");
}
__device__ __forceinline__ void cpcommit() { asm volatile("cp.async.commit_group;\n" ::: "memory"); }
__device__ __forceinline__ void cpwait0() { asm volatile("cp.async.wait_group 0;\n" ::: "memory"); }

__device__ __forceinline__ void ldsm4(uint32_t* r, uint32_t a) {
    asm volatile("ldmatrix.sync.aligned.m8n8.x4.shared.b16 {%0,%1,%2,%3}, [%4];\n"
        : "=r"(r[0]), "=r"(r[1]), "=r"(r[2]), "=r"(r[3]) : "r"(a));
}
__device__ __forceinline__ void ldsm4t(uint32_t* r, uint32_t a) {
    asm volatile("ldmatrix.sync.aligned.m8n8.x4.trans.shared.b16 {%0,%1,%2,%3}, [%4];\n"
        : "=r"(r[0]), "=r"(r[1]), "=r"(r[2]), "=r"(r[3]) : "r"(a));
}
__device__ __forceinline__ void mma16(float* c, const uint32_t* a, const uint32_t* b) {
    asm volatile("mma.sync.aligned.m16n8k16.row.col.f32.f16.f16.f32 "
        "{%0,%1,%2,%3}, {%4,%5,%6,%7}, {%8,%9}, {%0,%1,%2,%3};\n"
        : "+f"(c[0]), "+f"(c[1]), "+f"(c[2]), "+f"(c[3])
        : "r"(a[0]), "r"(a[1]), "r"(a[2]), "r"(a[3]), "r"(b[0]), "r"(b[1]));
}

template <int EPI, bool TB>
__global__ __launch_bounds__(256, 2) void hgemm(
    const __half* __restrict__ A, int lda, long long sA,
    const __half* __restrict__ B, int ldb, long long sB,
    float* __restrict__ Cf, __half* __restrict__ Ch, int ldc, long long sC,
    int M, int N, int K,
    const float* __restrict__ bias,
    const float* __restrict__ res, long long sRes)
{
    constexpr int BSZ = TB ? (BN * BSTT) : (BK * BSTN);
    __shared__ __half As[2][BM * AST];
    __shared__ __half Bs[2][BSZ];
    constexpr uint32_t ABYTES = BM * AST * 2;
    constexpr uint32_t BBYTES = BSZ * 2;

    const int z = blockIdx.z;
    A += (long long)z * sA; B += (long long)z * sB;

    const int tid = threadIdx.x, lane = tid & 31, wid = tid >> 5;
    const int wr = (wid >> 2) * 64, wc = (wid & 3) * 32;
    const int bRow = blockIdx.y * BM, bCol = blockIdx.x * BN;

    const uint32_t asB = (uint32_t)__cvta_generic_to_shared(&As[0][0]);
    const uint32_t bsB = (uint32_t)__cvta_generic_to_shared(&Bs[0][0]);

    // ---- global -> smem loaders: 512 x 16B chunks per tile, 2 per thread ----
    const int ar  = tid >> 2;            // 0..63
    const int ao8 = (tid & 3) * 8;       // k offset (fp16)
    const __half* Ag = A + (long long)(bRow + ar) * lda + ao8;
    const uint32_t asDst0 = asB + ((ar * AST + ao8) << 1);
    const uint32_t asDst1 = asB + (((ar + 64) * AST + ao8) << 1);

    const __half* Bg;
    uint32_t bsDst0, bsDst1;
    long long bStep1;
    if (TB) { // stored [n][k], stride 40
        Bg = B + (long long)(bCol + ar) * ldb + ao8;
        bsDst0 = bsB + ((ar * BSTT + ao8) << 1);
        bsDst1 = bsB + (((ar + 64) * BSTT + ao8) << 1);
        bStep1 = 64LL * ldb;
    } else {  // stored [k][n], stride 136
        const int bk  = tid >> 4;        // 0..15
        const int bo8 = (tid & 15) * 8;  // n offset
        Bg = B + (long long)bk * ldb + bCol + bo8;
        bsDst0 = bsB + ((bk * BSTN + bo8) << 1);
        bsDst1 = bsB + (((bk + 16) * BSTN + bo8) << 1);
        bStep1 = 16LL * ldb;
    }

    // ---- per-lane fragment base addresses ----
    const uint32_t aLane = asB + (((wr + (lane & 15)) * AST + ((lane >> 4) << 3)) << 1);
    const uint32_t bLaneT = bsB + (((wc + ((lane >> 4) << 3) + (lane & 7)) * BSTT
                                    + (((lane >> 3) & 1) << 3)) << 1);
    const uint32_t bLaneN = bsB + ((((((lane >> 3) & 1) << 3) + (lane & 7)) * BSTN
                                    + wc + ((lane >> 4) << 3)) << 1);
    const int g4 = lane >> 2, t4 = lane & 3;

    float acc[4][4][4];
#pragma unroll
    for (int i = 0; i < 4; i++)
#pragma unroll
        for (int j = 0; j < 4; j++)
#pragma unroll
            for (int r = 0; r < 4; r++) acc[i][j][r] = 0.f;

    const int nT = K / BK;

    // prefetch tile 0 -> buf 0
    cp16(asDst0, Ag);
    cp16(asDst1, Ag + 64LL * lda);
    cp16(bsDst0, Bg);
    cp16(bsDst1, Bg + bStep1);
    cpcommit();

    int buf = 0;
    for (int t = 0; t < nT; t++) {
        cpwait0();
        __syncthreads();
        if (t + 1 < nT) {
            const uint32_t ao = (buf ^ 1) ? ABYTES : 0;
            const uint32_t bo = (buf ^ 1) ? BBYTES : 0;
            const __half* ap = Ag + (t + 1) * BK;
            cp16(asDst0 + ao, ap);
            cp16(asDst1 + ao, ap + 64LL * lda);
            const __half* bp = TB ? (Bg + (t + 1) * BK)
                                  : (Bg + (long long)(t + 1) * BK * ldb);
            cp16(bsDst0 + bo, bp);
            cp16(bsDst1 + bo, bp + bStep1);
            cpcommit();
        }
        const uint32_t aOff = buf ? ABYTES : 0;
        const uint32_t bOff = buf ? BBYTES : 0;
#pragma unroll
        for (int ks = 0; ks < 2; ks++) {
            uint32_t af[4][4];
#pragma unroll
            for (int i = 0; i < 4; i++)
                ldsm4(af[i], aLane + aOff + (((i * 16) * AST + ks * 16) << 1));
            uint32_t bf[4][2];
#pragma unroll
            for (int jj = 0; jj < 2; jj++) {
                uint32_t r[4];
                if (TB) ldsm4(r, bLaneT + bOff + (((jj * 16) * BSTT + ks * 16) << 1));
                else    ldsm4t(r, bLaneN + bOff + (((ks * 16) * BSTN + jj * 16) << 1));
                bf[2 * jj][0]     = r[0];
                bf[2 * jj][1]     = r[1];
                bf[2 * jj + 1][0] = r[2];
                bf[2 * jj + 1][1] = r[3];
            }
#pragma unroll
            for (int i = 0; i < 4; i++)
#pragma unroll
                for (int j = 0; j < 4; j++)
                    mma16(acc[i][j], af[i], bf[j]);
        }
        buf ^= 1;
    }

    // ---- epilogue ----
    float* CfZ = Cf ? (Cf + (long long)z * sC) : nullptr;
    __half* ChZ = Ch ? (Ch + (long long)z * sC) : nullptr;
#pragma unroll
    for (int i = 0; i < 4; i++) {
#pragma unroll
        for (int h = 0; h < 2; h++) {
            const int gm = bRow + wr + i * 16 + g4 + h * 8;
#pragma unroll
            for (int j = 0; j < 4; j++) {
                const int gn = bCol + wc + j * 8 + t4 * 2;
                float v0 = acc[i][j][h * 2 + 0];
                float v1 = acc[i][j][h * 2 + 1];
                if (EPI == EPI_H16) {
                    *(__half2*)&ChZ[(long long)gm * ldc + gn] =
                        __floats2half2_rn(v0, v1);
                } else if (EPI == EPI_SCORES) {
                    v0 *= 0.5f; v1 *= 0.5f;
                    v0 = (gn >= gm && v0 != 0.0f) ? v0 : -9e15f;
                    v1 = (gn + 1 >= gm && v1 != 0.0f) ? v1 : -9e15f;
                    *(float2*)&CfZ[(long long)gm * ldc + gn] = make_float2(v0, v1);
                } else if (EPI == EPI_DUAL) {
                    const float2 rr = *(const float2*)&res[(long long)gm * ldc + gn];
                    v0 += bias[gn] + rr.x;
                    v1 += bias[gn + 1] + rr.y;
                    *(float2*)&CfZ[(long long)gm * ldc + gn] = make_float2(v0, v1);
                    *(__half2*)&ChZ[(long long)gm * ldc + gn] =
                        __floats2half2_rn(v0, v1);
                } else if (EPI == EPI_RELU_H16) {
                    v0 = fmaxf(v0 + bias[gn], 0.f);
                    v1 = fmaxf(v1 + bias[gn + 1], 0.f);
                    *(__half2*)&ChZ[(long long)gm * ldc + gn] =
                        __floats2half2_rn(v0, v1);
                } else { // EPI_RES_F32
                    const float2 rr = *(const float2*)&res[(long long)gm * ldc + gn];
                    v0 += bias[gn] + rr.x;
                    v1 += bias[gn + 1] + rr.y;
                    *(float2*)&CfZ[(long long)gm * ldc + gn] = make_float2(v0, v1);
                }
            }
        }
    }
}

// ---------------- fp32 -> fp16 conversion ----------------
__global__ __launch_bounds__(256) void cvt_f2h(const float* __restrict__ in,
                                               __half* __restrict__ out, int n)
{
    const int i = (blockIdx.x * 256 + threadIdx.x) * 4;
    if (i < n) {
        const float4 v = *(const float4*)(in + i);
        *(__half2*)(out + i)     = __floats2half2_rn(v.x, v.y);
        *(__half2*)(out + i + 2) = __floats2half2_rn(v.z, v.w);
    }
}

// ---------------- row softmax over 2048 (fp32 in -> fp16 out) ----------------
__inline__ __device__ float warpMaxf(float v) {
#pragma unroll
    for (int o = 16; o > 0; o >>= 1) v = fmaxf(v, __shfl_xor_sync(0xffffffffu, v, o));
    return v;
}
__inline__ __device__ float warpSumf(float v) {
#pragma unroll
    for (int o = 16; o > 0; o >>= 1) v += __shfl_xor_sync(0xffffffffu, v, o);
    return v;
}

__global__ __launch_bounds__(256) void softmax2048(const float* __restrict__ S,
                                                   __half* __restrict__ O)
{
    __shared__ float red[8];
    __shared__ float bcast;
    const long long row = blockIdx.x;
    const float* p = S + row * 2048;
    const int tid = threadIdx.x;
    const int lane = tid & 31, wid = tid >> 5;

    float v[8];
    *(float4*)&v[0] = *(const float4*)(p + tid * 8);
    *(float4*)&v[4] = *(const float4*)(p + tid * 8 + 4);

    float m = v[0];
#pragma unroll
    for (int i = 1; i < 8; i++) m = fmaxf(m, v[i]);
    m = warpMaxf(m);
    if (lane == 0) red[wid] = m;
    __syncthreads();
    if (tid == 0) {
        float t = red[0];
#pragma unroll
        for (int i = 1; i < 8; i++) t = fmaxf(t, red[i]);
        bcast = t;
    }
    __syncthreads();
    m = bcast;

    float s = 0.f;
#pragma unroll
    for (int i = 0; i < 8; i++) { v[i] = expf(v[i] - m); s += v[i]; }
    s = warpSumf(s);
    __syncthreads();
    if (lane == 0) red[wid] = s;
    __syncthreads();
    if (tid == 0) {
        float t = 0.f;
#pragma unroll
        for (int i = 0; i < 8; i++) t += red[i];
        bcast = t;
    }
    __syncthreads();
    const float inv = 1.0f / bcast;

    union { uint4 u; __half2 h[4]; } pk;
#pragma unroll
    for (int k = 0; k < 4; k++)
        pk.h[k] = __floats2half2_rn(v[2 * k] * inv, v[2 * k + 1] * inv);
    *(uint4*)(O + row * 2048 + tid * 8) = pk.u;
}

// ---------------- launch ----------------
extern "C" void kernel_launch(void* const* d_in, const int* in_sizes, int n_in,
                              void* d_out, int out_size)
{
    const float* x     = (const float*)d_in[0];
    const float* wqkv  = (const float*)d_in[1];
    const float* w_lin = (const float*)d_in[2];
    const float* b_lin = (const float*)d_in[3];
    const float* w_ff1 = (const float*)d_in[4];
    const float* b_ff1 = (const float*)d_in[5];
    const float* w_ff2 = (const float*)d_in[6];
    const float* b_ff2 = (const float*)d_in[7];
    float* out = (float*)d_out;

    static __half *xh=nullptr,*wqkvh,*wlh,*wf1h,*wf2h,*qkvh,*atth,*attnh,*x2h,*hh;
    static float *scores, *x2;
    if (!xh) {
        void* p;
        cudaGetSymbolAddress(&p, g_xh);    xh    = (__half*)p;
        cudaGetSymbolAddress(&p, g_wqkvh); wqkvh = (__half*)p;
        cudaGetSymbolAddress(&p, g_wlh);   wlh   = (__half*)p;
        cudaGetSymbolAddress(&p, g_wf1h);  wf1h  = (__half*)p;
        cudaGetSymbolAddress(&p, g_wf2h);  wf2h  = (__half*)p;
        cudaGetSymbolAddress(&p, g_qkvh);  qkvh  = (__half*)p;
        cudaGetSymbolAddress(&p, g_atth);  atth  = (__half*)p;
        cudaGetSymbolAddress(&p, g_attnh); attnh = (__half*)p;
        cudaGetSymbolAddress(&p, g_x2h);   x2h   = (__half*)p;
        cudaGetSymbolAddress(&p, g_hh);    hh    = (__half*)p;
        cudaGetSymbolAddress(&p, g_scores); scores = (float*)p;
        cudaGetSymbolAddress(&p, g_x2);     x2     = (float*)p;
    }

    const long long sQKV = (long long)Ss * 3 * Dd;
    const long long sSC  = (long long)Ss * Ss;
    const long long sAO  = (long long)Ss * Dd;
    dim3 blk(256);

    // conversions
    cvt_f2h<<<(Bb * Ss * Dd) / 1024, 256>>>(x, xh, Bb * Ss * Dd);
    cvt_f2h<<<(Dd * 3 * Dd) / 1024, 256>>>(wqkv, wqkvh, Dd * 3 * Dd);
    cvt_f2h<<<(Dd * Dd) / 1024, 256>>>(w_lin, wlh, Dd * Dd);
    cvt_f2h<<<(Dd * Dd) / 1024, 256>>>(w_ff1, wf1h, Dd * Dd);
    cvt_f2h<<<(Dd * Dd) / 1024, 256>>>(w_ff2, wf2h, Dd * Dd);

    // G1: qkv(fp16) = x @ wqkv  [8192 x 3072] K=1024
    hgemm<EPI_H16, false><<<dim3(3072 / BN, (Bb * Ss) / BM, 1), blk>>>(
        xh, Dd, 0, wqkvh, 3 * Dd, 0, nullptr, qkvh, 3 * Dd, 0,
        Bb * Ss, 3 * Dd, Dd, nullptr, nullptr, 0);

    // G2: scores(fp32) = 0.5 * Q @ K^T + mask  (per batch) K=1024
    hgemm<EPI_SCORES, true><<<dim3(Ss / BN, Ss / BM, Bb), blk>>>(
        qkvh, 3 * Dd, sQKV,
        qkvh + Dd, 3 * Dd, sQKV,
        scores, nullptr, Ss, sSC,
        Ss, Ss, Dd, nullptr, nullptr, 0);

    // softmax -> att(fp16)
    softmax2048<<<Bb * Ss, 256>>>(scores, atth);

    // G3: attn(fp16) = att @ V  (per batch) K=2048
    hgemm<EPI_H16, false><<<dim3(Dd / BN, Ss / BM, Bb), blk>>>(
        atth, Ss, sSC,
        qkvh + 2 * Dd, 3 * Dd, sQKV,
        nullptr, attnh, Dd, sAO,
        Ss, Dd, Ss, nullptr, nullptr, 0);

    // G4: x2(fp32 + fp16) = attn @ w_lin + b_lin + x
    hgemm<EPI_DUAL, false><<<dim3(Dd / BN, (Bb * Ss) / BM, 1), blk>>>(
        attnh, Dd, 0, wlh, Dd, 0, x2, x2h, Dd, 0,
        Bb * Ss, Dd, Dd, b_lin, x, 0);

    // G5: h(fp16) = relu(x2 @ w_ff1 + b_ff1)
    hgemm<EPI_RELU_H16, false><<<dim3(Dd / BN, (Bb * Ss) / BM, 1), blk>>>(
        x2h, Dd, 0, wf1h, Dd, 0, nullptr, hh, Dd, 0,
        Bb * Ss, Dd, Dd, b_ff1, nullptr, 0);

    // G6: out(fp32) = h @ w_ff2 + b_ff2 + x2
    hgemm<EPI_RES_F32, false><<<dim3(Dd / BN, (Bb * Ss) / BM, 1), blk>>>(
        hh, Dd, 0, wf2h, Dd, 0, out, nullptr, Dd, 0,
        Bb * Ss, Dd, Dd, b_ff2, x2, 0);
}

// round 8
// speedup vs baseline: 7.4095x; 1.1874x over previous
#include <cuda_runtime.h>
#include <cuda_fp16.h>
#include <cstdint>

// ---------------- scratch (device globals; no allocation allowed) ----------------
#define Bb 4
#define Ss 2048
#define Dd 1024
__device__ unsigned short g_xh[(long long)Bb * Ss * Dd];
__device__ unsigned short g_wqkvh[(long long)Dd * 3 * Dd];
__device__ unsigned short g_wlh[(long long)Dd * Dd];
__device__ unsigned short g_wf1h[(long long)Dd * Dd];
__device__ unsigned short g_wf2h[(long long)Dd * Dd];
__device__ unsigned short g_qkvh[(long long)Bb * Ss * 3 * Dd];
__device__ float          g_scores[(long long)Bb * Ss * Ss];
__device__ unsigned short g_atth[(long long)Bb * Ss * Ss];
__device__ unsigned short g_attnh[(long long)Bb * Ss * Dd];
__device__ float          g_x2[(long long)Bb * Ss * Dd];
__device__ unsigned short g_x2h[(long long)Bb * Ss * Dd];
__device__ unsigned short g_hh[(long long)Bb * Ss * Dd];

// ---------------- fp16 tensor-core GEMM: 128x128x32, 256 threads, 3-stage ----------------
#define BM 128
#define BN 128
#define BK 32
#define AST 40     // A smem row stride (fp16): conflict-free ldmatrix phases
#define BSTT 40    // B smem stride, TB ([N][K]) layout
#define BSTN 136   // B smem stride, non-TB ([K][N]) layout
#define NSTG 3

enum { EPI_H16 = 0, EPI_SCORES = 1, EPI_DUAL = 2, EPI_RELU_H16 = 3, EPI_RES_F32 = 4 };
enum { TRI_NONE = 0, TRI_SKIP_LOWER = 1, TRI_KSTART = 2 };

__device__ __forceinline__ void cp16(uint32_t dst, const void* src) {
    asm volatile("cp.async.cg.shared.global [%0], [%1], 16;\n" :: "r"(dst), "l"(src) : "memory");
}
__device__ __forceinline__ void cpcommit() { asm volatile("cp.async.commit_group;\n" ::: "memory"); }
__device__ __forceinline__ void cpwait0() { asm volatile("cp.async.wait_group 0;\n" ::: "memory"); }
__device__ __forceinline__ void cpwait1() { asm volatile("cp.async.wait_group 1;\n" ::: "memory"); }

__device__ __forceinline__ void ldsm4(uint32_t* r, uint32_t a) {
    asm volatile("ldmatrix.sync.aligned.m8n8.x4.shared.b16 {%0,%1,%2,%3}, [%4];\n"
        : "=r"(r[0]), "=r"(r[1]), "=r"(r[2]), "=r"(r[3]) : "r"(a));
}
__device__ __forceinline__ void ldsm4t(uint32_t* r, uint32_t a) {
    asm volatile("ldmatrix.sync.aligned.m8n8.x4.trans.shared.b16 {%0,%1,%2,%3}, [%4];\n"
        : "=r"(r[0]), "=r"(r[1]), "=r"(r[2]), "=r"(r[3]) : "r"(a));
}
__device__ __forceinline__ void mma16(float* c, const uint32_t* a, const uint32_t* b) {
    asm volatile("mma.sync.aligned.m16n8k16.row.col.f32.f16.f16.f32 "
        "{%0,%1,%2,%3}, {%4,%5,%6,%7}, {%8,%9}, {%0,%1,%2,%3};\n"
        : "+f"(c[0]), "+f"(c[1]), "+f"(c[2]), "+f"(c[3])
        : "r"(a[0]), "r"(a[1]), "r"(a[2]), "r"(a[3]), "r"(b[0]), "r"(b[1]));
}

template <bool TB>
struct SmemCfg {
    static constexpr int BSZ = TB ? (BN * BSTT) : (BK * BSTN);
    static constexpr uint32_t ABYTES = BM * AST * 2;
    static constexpr uint32_t BBYTES = BSZ * 2;
    static constexpr size_t TOTAL = (size_t)NSTG * (ABYTES + BBYTES);
};

template <int EPI, bool TB, int TRI>
__global__ __launch_bounds__(256, 2) void hgemm(
    const __half* __restrict__ A, int lda, long long sA,
    const __half* __restrict__ B, int ldb, long long sB,
    float* __restrict__ Cf, __half* __restrict__ Ch, int ldc, long long sC,
    int M, int N, int K,
    const float* __restrict__ bias,
    const float* __restrict__ res, long long sRes)
{
    constexpr uint32_t ABYTES = SmemCfg<TB>::ABYTES;
    constexpr uint32_t BBYTES = SmemCfg<TB>::BBYTES;
    extern __shared__ __half smemDyn[];

    const int bRow = blockIdx.y * BM, bCol = blockIdx.x * BN;
    if (TRI == TRI_SKIP_LOWER) { if (bCol + BN <= bRow) return; }
    const int kStart = (TRI == TRI_KSTART) ? bRow : 0;

    const int z = blockIdx.z;
    A += (long long)z * sA; B += (long long)z * sB;

    const int tid = threadIdx.x, lane = tid & 31, wid = tid >> 5;
    const int wr = (wid >> 2) * 64, wc = (wid & 3) * 32;

    const uint32_t asB = (uint32_t)__cvta_generic_to_shared(smemDyn);
    const uint32_t bsB = asB + NSTG * ABYTES;

    // ---- loaders: 16B chunks, 2 per thread per operand ----
    const int ar  = tid >> 2;            // 0..63
    const int ao8 = (tid & 3) * 8;       // k offset (fp16)
    const __half* Ag = A + (long long)(bRow + ar) * lda + kStart + ao8;
    const uint32_t asDst0 = asB + ((ar * AST + ao8) << 1);
    const uint32_t asDst1 = asB + (((ar + 64) * AST + ao8) << 1);

    const __half* Bg;
    uint32_t bsDst0, bsDst1;
    long long bStep1;
    if (TB) { // stored [n][k]
        Bg = B + (long long)(bCol + ar) * ldb + kStart + ao8;
        bsDst0 = bsB + ((ar * BSTT + ao8) << 1);
        bsDst1 = bsB + (((ar + 64) * BSTT + ao8) << 1);
        bStep1 = 64LL * ldb;
    } else {  // stored [k][n]
        const int bk  = tid >> 4;        // 0..15
        const int bo8 = (tid & 15) * 8;  // n offset
        Bg = B + (long long)(kStart + bk) * ldb + bCol + bo8;
        bsDst0 = bsB + ((bk * BSTN + bo8) << 1);
        bsDst1 = bsB + (((bk + 16) * BSTN + bo8) << 1);
        bStep1 = 16LL * ldb;
    }

    // ---- per-lane fragment base addresses ----
    const uint32_t aLane = asB + (((wr + (lane & 15)) * AST + ((lane >> 4) << 3)) << 1);
    const uint32_t bLaneT = bsB + (((wc + ((lane >> 4) << 3) + (lane & 7)) * BSTT
                                    + (((lane >> 3) & 1) << 3)) << 1);
    const uint32_t bLaneN = bsB + ((((((lane >> 3) & 1) << 3) + (lane & 7)) * BSTN
                                    + wc + ((lane >> 4) << 3)) << 1);
    const int g4 = lane >> 2, t4 = lane & 3;

    float acc[4][4][4];
#pragma unroll
    for (int i = 0; i < 4; i++)
#pragma unroll
        for (int j = 0; j < 4; j++)
#pragma unroll
            for (int r = 0; r < 4; r++) acc[i][j][r] = 0.f;

    const int nT = (K - kStart) / BK;

    auto ldTile = [&](int stg, int t) {
        const uint32_t ao = (uint32_t)stg * ABYTES;
        const uint32_t bo = (uint32_t)stg * BBYTES;
        const __half* ap = Ag + t * BK;
        cp16(asDst0 + ao, ap);
        cp16(asDst1 + ao, ap + 64LL * lda);
        const __half* bp = TB ? (Bg + t * BK) : (Bg + (long long)t * BK * ldb);
        cp16(bsDst0 + bo, bp);
        cp16(bsDst1 + bo, bp + bStep1);
        cpcommit();
    };

    // prefetch stages 0,1
    ldTile(0, 0);
    if (nT > 1) ldTile(1, 1);

    int stg = 0;
    for (int t = 0; t < nT; t++) {
        if (t + 1 < nT) cpwait1(); else cpwait0();
        __syncthreads();
        if (t + 2 < nT) {
            int ns = stg + 2; if (ns >= NSTG) ns -= NSTG;
            ldTile(ns, t + 2);
        }
        const uint32_t aOff = (uint32_t)stg * ABYTES;
        const uint32_t bOff = (uint32_t)stg * BBYTES;
#pragma unroll
        for (int ks = 0; ks < 2; ks++) {
            uint32_t af[4][4];
#pragma unroll
            for (int i = 0; i < 4; i++)
                ldsm4(af[i], aLane + aOff + (((i * 16) * AST + ks * 16) << 1));
            uint32_t bf[4][2];
#pragma unroll
            for (int jj = 0; jj < 2; jj++) {
                uint32_t r[4];
                if (TB) ldsm4(r, bLaneT + bOff + (((jj * 16) * BSTT + ks * 16) << 1));
                else    ldsm4t(r, bLaneN + bOff + (((ks * 16) * BSTN + jj * 16) << 1));
                bf[2 * jj][0]     = r[0];
                bf[2 * jj][1]     = r[1];
                bf[2 * jj + 1][0] = r[2];
                bf[2 * jj + 1][1] = r[3];
            }
#pragma unroll
            for (int i = 0; i < 4; i++)
#pragma unroll
                for (int j = 0; j < 4; j++)
                    mma16(acc[i][j], af[i], bf[j]);
        }
        stg++; if (stg >= NSTG) stg = 0;
    }

    // ---- epilogue ----
    float* CfZ = Cf ? (Cf + (long long)z * sC) : nullptr;
    __half* ChZ = Ch ? (Ch + (long long)z * sC) : nullptr;
#pragma unroll
    for (int i = 0; i < 4; i++) {
#pragma unroll
        for (int h = 0; h < 2; h++) {
            const int gm = bRow + wr + i * 16 + g4 + h * 8;
#pragma unroll
            for (int j = 0; j < 4; j++) {
                const int gn = bCol + wc + j * 8 + t4 * 2;
                float v0 = acc[i][j][h * 2 + 0];
                float v1 = acc[i][j][h * 2 + 1];
                if (EPI == EPI_H16) {
                    *(__half2*)&ChZ[(long long)gm * ldc + gn] =
                        __floats2half2_rn(v0, v1);
                } else if (EPI == EPI_SCORES) {
                    v0 *= 0.5f; v1 *= 0.5f;
                    v0 = (gn >= gm && v0 != 0.0f) ? v0 : -9e15f;
                    v1 = (gn + 1 >= gm && v1 != 0.0f) ? v1 : -9e15f;
                    *(float2*)&CfZ[(long long)gm * ldc + gn] = make_float2(v0, v1);
                } else if (EPI == EPI_DUAL) {
                    const float2 rr = *(const float2*)&res[(long long)gm * ldc + gn];
                    v0 += bias[gn] + rr.x;
                    v1 += bias[gn + 1] + rr.y;
                    *(float2*)&CfZ[(long long)gm * ldc + gn] = make_float2(v0, v1);
                    *(__half2*)&ChZ[(long long)gm * ldc + gn] =
                        __floats2half2_rn(v0, v1);
                } else if (EPI == EPI_RELU_H16) {
                    v0 = fmaxf(v0 + bias[gn], 0.f);
                    v1 = fmaxf(v1 + bias[gn + 1], 0.f);
                    *(__half2*)&ChZ[(long long)gm * ldc + gn] =
                        __floats2half2_rn(v0, v1);
                } else { // EPI_RES_F32
                    const float2 rr = *(const float2*)&res[(long long)gm * ldc + gn];
                    v0 += bias[gn] + rr.x;
                    v1 += bias[gn + 1] + rr.y;
                    *(float2*)&CfZ[(long long)gm * ldc + gn] = make_float2(v0, v1);
                }
            }
        }
    }
}

// ---------------- fp32 -> fp16 conversion ----------------
__global__ __launch_bounds__(256) void cvt_f2h(const float* __restrict__ in,
                                               __half* __restrict__ out, int n)
{
    const int i = (blockIdx.x * 256 + threadIdx.x) * 4;
    if (i < n) {
        const float4 v = *(const float4*)(in + i);
        *(__half2*)(out + i)     = __floats2half2_rn(v.x, v.y);
        *(__half2*)(out + i + 2) = __floats2half2_rn(v.z, v.w);
    }
}

// ---------------- triangular row softmax (reads/writes only t >= r) ----------------
__inline__ __device__ float warpMaxf(float v) {
#pragma unroll
    for (int o = 16; o > 0; o >>= 1) v = fmaxf(v, __shfl_xor_sync(0xffffffffu, v, o));
    return v;
}
__inline__ __device__ float warpSumf(float v) {
#pragma unroll
    for (int o = 16; o > 0; o >>= 1) v += __shfl_xor_sync(0xffffffffu, v, o);
    return v;
}

__global__ __launch_bounds__(256) void softmax_tri(const float* __restrict__ S,
                                                   __half* __restrict__ O)
{
    __shared__ float red[8];
    __shared__ float bcast;
    const long long row = blockIdx.x;
    const int s = (int)(row & (Ss - 1));
    const int r = s & ~127;              // start of valid region
    const float* p = S + row * Ss;
    const int tid = threadIdx.x;
    const int lane = tid & 31, wid = tid >> 5;

    const int idx = r + tid * 8;
    const bool act = idx < Ss;

    float v[8];
    if (act) {
        *(float4*)&v[0] = *(const float4*)(p + idx);
        *(float4*)&v[4] = *(const float4*)(p + idx + 4);
    }

    float m = -__int_as_float(0x7f800000);  // -inf
    if (act) {
        m = v[0];
#pragma unroll
        for (int i = 1; i < 8; i++) m = fmaxf(m, v[i]);
    }
    m = warpMaxf(m);
    if (lane == 0) red[wid] = m;
    __syncthreads();
    if (tid == 0) {
        float t = red[0];
#pragma unroll
        for (int i = 1; i < 8; i++) t = fmaxf(t, red[i]);
        bcast = t;
    }
    __syncthreads();
    m = bcast;

    float sum = 0.f;
    if (act) {
#pragma unroll
        for (int i = 0; i < 8; i++) { v[i] = expf(v[i] - m); sum += v[i]; }
    }
    sum = warpSumf(sum);
    __syncthreads();
    if (lane == 0) red[wid] = sum;
    __syncthreads();
    if (tid == 0) {
        float t = 0.f;
#pragma unroll
        for (int i = 0; i < 8; i++) t += red[i];
        bcast = t;
    }
    __syncthreads();
    const float inv = 1.0f / bcast;

    if (act) {
        union { uint4 u; __half2 h[4]; } pk;
#pragma unroll
        for (int k = 0; k < 4; k++)
            pk.h[k] = __floats2half2_rn(v[2 * k] * inv, v[2 * k + 1] * inv);
        *(uint4*)(O + row * Ss + idx) = pk.u;
    }
}

// ---------------- launch ----------------
extern "C" void kernel_launch(void* const* d_in, const int* in_sizes, int n_in,
                              void* d_out, int out_size)
{
    const float* x     = (const float*)d_in[0];
    const float* wqkv  = (const float*)d_in[1];
    const float* w_lin = (const float*)d_in[2];
    const float* b_lin = (const float*)d_in[3];
    const float* w_ff1 = (const float*)d_in[4];
    const float* b_ff1 = (const float*)d_in[5];
    const float* w_ff2 = (const float*)d_in[6];
    const float* b_ff2 = (const float*)d_in[7];
    float* out = (float*)d_out;

    constexpr size_t SMEM_N = SmemCfg<false>::TOTAL;  // 56832
    constexpr size_t SMEM_T = SmemCfg<true>::TOTAL;   // 61440

    static __half *xh=nullptr,*wqkvh,*wlh,*wf1h,*wf2h,*qkvh,*atth,*attnh,*x2h,*hh;
    static float *scores, *x2;
    if (!xh) {
        void* p;
        cudaGetSymbolAddress(&p, g_xh);    xh    = (__half*)p;
        cudaGetSymbolAddress(&p, g_wqkvh); wqkvh = (__half*)p;
        cudaGetSymbolAddress(&p, g_wlh);   wlh   = (__half*)p;
        cudaGetSymbolAddress(&p, g_wf1h);  wf1h  = (__half*)p;
        cudaGetSymbolAddress(&p, g_wf2h);  wf2h  = (__half*)p;
        cudaGetSymbolAddress(&p, g_qkvh);  qkvh  = (__half*)p;
        cudaGetSymbolAddress(&p, g_atth);  atth  = (__half*)p;
        cudaGetSymbolAddress(&p, g_attnh); attnh = (__half*)p;
        cudaGetSymbolAddress(&p, g_x2h);   x2h   = (__half*)p;
        cudaGetSymbolAddress(&p, g_hh);    hh    = (__half*)p;
        cudaGetSymbolAddress(&p, g_scores); scores = (float*)p;
        cudaGetSymbolAddress(&p, g_x2);     x2     = (float*)p;

        cudaFuncSetAttribute(hgemm<EPI_H16,      false, TRI_NONE>,
                             cudaFuncAttributeMaxDynamicSharedMemorySize, SMEM_N);
        cudaFuncSetAttribute(hgemm<EPI_SCORES,   true,  TRI_SKIP_LOWER>,
                             cudaFuncAttributeMaxDynamicSharedMemorySize, SMEM_T);
        cudaFuncSetAttribute(hgemm<EPI_H16,      false, TRI_KSTART>,
                             cudaFuncAttributeMaxDynamicSharedMemorySize, SMEM_N);
        cudaFuncSetAttribute(hgemm<EPI_DUAL,     false, TRI_NONE>,
                             cudaFuncAttributeMaxDynamicSharedMemorySize, SMEM_N);
        cudaFuncSetAttribute(hgemm<EPI_RELU_H16, false, TRI_NONE>,
                             cudaFuncAttributeMaxDynamicSharedMemorySize, SMEM_N);
        cudaFuncSetAttribute(hgemm<EPI_RES_F32,  false, TRI_NONE>,
                             cudaFuncAttributeMaxDynamicSharedMemorySize, SMEM_N);
    }

    const long long sQKV = (long long)Ss * 3 * Dd;
    const long long sSC  = (long long)Ss * Ss;
    const long long sAO  = (long long)Ss * Dd;
    dim3 blk(256);

    // conversions
    cvt_f2h<<<(Bb * Ss * Dd) / 1024, 256>>>(x, xh, Bb * Ss * Dd);
    cvt_f2h<<<(Dd * 3 * Dd) / 1024, 256>>>(wqkv, wqkvh, Dd * 3 * Dd);
    cvt_f2h<<<(Dd * Dd) / 1024, 256>>>(w_lin, wlh, Dd * Dd);
    cvt_f2h<<<(Dd * Dd) / 1024, 256>>>(w_ff1, wf1h, Dd * Dd);
    cvt_f2h<<<(Dd * Dd) / 1024, 256>>>(w_ff2, wf2h, Dd * Dd);

    // G1: qkv(fp16) = x @ wqkv  [8192 x 3072] K=1024
    hgemm<EPI_H16, false, TRI_NONE><<<dim3(3072 / BN, (Bb * Ss) / BM, 1), blk, SMEM_N>>>(
        xh, Dd, 0, wqkvh, 3 * Dd, 0, nullptr, qkvh, 3 * Dd, 0,
        Bb * Ss, 3 * Dd, Dd, nullptr, nullptr, 0);

    // G2: scores(fp32) = 0.5 * Q @ K^T + mask (upper tiles only)
    hgemm<EPI_SCORES, true, TRI_SKIP_LOWER><<<dim3(Ss / BN, Ss / BM, Bb), blk, SMEM_T>>>(
        qkvh, 3 * Dd, sQKV,
        qkvh + Dd, 3 * Dd, sQKV,
        scores, nullptr, Ss, sSC,
        Ss, Ss, Dd, nullptr, nullptr, 0);

    // softmax -> att(fp16), valid region only
    softmax_tri<<<Bb * Ss, 256>>>(scores, atth);

    // G3: attn(fp16) = att @ V, K starts at row block
    hgemm<EPI_H16, false, TRI_KSTART><<<dim3(Dd / BN, Ss / BM, Bb), blk, SMEM_N>>>(
        atth, Ss, sSC,
        qkvh + 2 * Dd, 3 * Dd, sQKV,
        nullptr, attnh, Dd, sAO,
        Ss, Dd, Ss, nullptr, nullptr, 0);

    // G4: x2(fp32 + fp16) = attn @ w_lin + b_lin + x
    hgemm<EPI_DUAL, false, TRI_NONE><<<dim3(Dd / BN, (Bb * Ss) / BM, 1), blk, SMEM_N>>>(
        attnh, Dd, 0, wlh, Dd, 0, x2, x2h, Dd, 0,
        Bb * Ss, Dd, Dd, b_lin, x, 0);

    // G5: h(fp16) = relu(x2 @ w_ff1 + b_ff1)
    hgemm<EPI_RELU_H16, false, TRI_NONE><<<dim3(Dd / BN, (Bb * Ss) / BM, 1), blk, SMEM_N>>>(
        x2h, Dd, 0, wf1h, Dd, 0, nullptr, hh, Dd, 0,
        Bb * Ss, Dd, Dd, b_ff1, nullptr, 0);

    // G6: out(fp32) = h @ w_ff2 + b_ff2 + x2
    hgemm<EPI_RES_F32, false, TRI_NONE><<<dim3(Dd / BN, (Bb * Ss) / BM, 1), blk, SMEM_N>>>(
        hh, Dd, 0, wf2h, Dd, 0, out, nullptr, Dd, 0,
        Bb * Ss, Dd, Dd, b_ff2, x2, 0);
}